// round 11
// baseline (speedup 1.0000x reference)
#include <cuda_runtime.h>

namespace {
constexpr int BS = 4, P = 4096, HW = 512 * 512;
constexpr int NT = 32;                      // 128-wide all-pairs tiles
constexpr int NTILES = NT * (NT + 1) / 2;   // 528
constexpr int APB = BS * NTILES;            // 2112 all-pairs blocks
constexpr int NCLS = 7, CAP = 768;          // class capacity (~8 sigma)
constexpr int NTC = 6;                      // 128-wide class tiles
constexpr int CT = NTC * (NTC + 1) / 2;     // 21
constexpr int SLB = BS * NCLS * CT;         // 588 same-label blocks
constexpr int GRID1 = 148;                  // 4 prep + 144 gather (>=148: no throttle)
constexpr int GRID2 = APB + SLB;            // 2700
constexpr double NP = 8386560.0;            // P*(P-1)/2
}

__device__ float  g_ap[BS][P];              // a - 0.9 (sample order)
__device__ float  g_nb[BS][P];              // -relu(a)
__device__ float  g_cls_a [BS][NCLS * CAP]; // label-grouped a (stable order)
__device__ float  g_cls_nb[BS][NCLS * CAP]; // label-grouped -relu(a)
__device__ int    g_Mc[BS][NCLS];           // padded class sizes (mult of 128)
__device__ double g_acc;                    // zero-init; reset each replay
__device__ unsigned g_cnt;

// =========== kernel 1: gather-once + label partition (no cross-block waits) =
__global__ __launch_bounds__(256) void k1(const float* __restrict__ yp,
                                          const int*   __restrict__ yt,
                                          const int*   __restrict__ sm) {
    __shared__ unsigned long long sA[256], sB[256];
    int bid = blockIdx.x, tid = threadIdx.x;

    if (bid >= 4) {
        // ---- gather blocks: one scattered load per element, done ONCE ------
        for (int i = (bid - 4) * 256 + tid; i < BS * P; i += 144 * 256) {
            int b = i >> 12, p = i & (P - 1);
            int idx = sm[i];
            float a = yp[b * HW + idx];
            g_ap[b][p] = a - 0.9f;
            g_nb[b][p] = -fmaxf(a, 0.0f);
        }
        return;
    }

    // ---- prep blocks (0..3): stable label partition for batch b ------------
    int b = bid;
    float av[16], nbv[16]; int lb[16];
    int base = tid * 16;
    #pragma unroll
    for (int k = 0; k < 16; k++) {
        int idx = sm[b * P + base + k];
        float a = yp[b * HW + idx];
        int   t = yt[b * HW + idx];
        av[k]  = a;
        nbv[k] = -fmaxf(a, 0.0f);
        lb[k]  = min(max(t, 1), 7);
    }
    unsigned long long cA = 0ull, cB = 0ull;
    #pragma unroll
    for (int k = 0; k < 16; k++) {
        int c = lb[k];
        if (c <= 4) cA += 1ull << ((c - 1) * 16);
        else        cB += 1ull << ((c - 5) * 16);
    }
    sA[tid] = cA; sB[tid] = cB;
    for (int off = 1; off < 256; off <<= 1) {          // inclusive scan
        __syncthreads();
        unsigned long long vA = (tid >= off) ? sA[tid - off] : 0ull;
        unsigned long long vB = (tid >= off) ? sB[tid - off] : 0ull;
        __syncthreads();
        sA[tid] += vA; sB[tid] += vB;
    }
    __syncthreads();
    unsigned long long exA = sA[tid] - cA, exB = sB[tid] - cB;
    unsigned long long totA = sA[255],    totB = sB[255];

    for (int i = tid; i < NCLS * CAP; i += 256) {
        g_cls_a [b][i] = -1e30f;       // pad pair contributes exactly -0.95 to G
        g_cls_nb[b][i] = -1e30f;
    }
    __syncthreads();

    unsigned long long curA = exA, curB = exB;
    #pragma unroll
    for (int k = 0; k < 16; k++) {
        int c = lb[k], off;
        if (c <= 4) { int sh = (c - 1) * 16; off = (int)((curA >> sh) & 0xFFFF); curA += 1ull << sh; }
        else        { int sh = (c - 5) * 16; off = (int)((curB >> sh) & 0xFFFF); curB += 1ull << sh; }
        if (off < CAP) {
            int slot = (c - 1) * CAP + off;
            g_cls_a [b][slot] = av[k];
            g_cls_nb[b][slot] = nbv[k];
        }
    }
    if (tid == 0) {
        double fake = 0.0;
        for (int c = 0; c < NCLS; c++) {
            int n = (c < 4) ? (int)((totA >> (c * 16)) & 0xFFFF)
                            : (int)((totB >> ((c - 4) * 16)) & 0xFFFF);
            if (n > CAP) n = CAP;
            int M = ((n + 127) / 128) * 128;
            g_Mc[b][c] = M;
            fake += 0.5 * ((double)M * (M - 1) - (double)n * (n - 1));
        }
        atomicAdd(&g_acc, 0.95 * fake);   // pad pairs each contributed -0.95
    }
}

// =========== kernel 2: all-pairs + same-label from compact arrays ===========
__global__ __launch_bounds__(256) void k2(float* __restrict__ out) {
    __shared__ float s_a[128];  __shared__ float s_nc[128];
    __shared__ float s_part[8];
    int bid = blockIdx.x, tid = threadIdx.x;
    float contrib = 0.0f;

    if (bid < APB) {
        // ---- all-pairs 128x128 tile, 8x8 register micro-tile ---------------
        // per pair: loss-0.05 = 5*relu(v)^2 - max(v,-0.9), v=(a_i-0.9)-relu(a_j)
        int b = bid / NTILES, t = bid % NTILES;
        int ti = 0;
        while (t >= NT - ti) { t -= NT - ti; ti++; }
        int tj = ti + t;

        if (tid < 128) s_a[tid]        = g_ap[b][ti * 128 + tid];
        else           s_nc[tid - 128] = g_nb[b][tj * 128 + (tid - 128)];
        __syncthreads();

        int tx = tid & 15, ty = tid >> 4;
        float a[8], nc[8];
        #pragma unroll
        for (int k = 0; k < 8; k++) {
            a[k]  = s_a[ty * 8 + k];
            nc[k] = s_nc[tx * 8 + k];
        }

        float aU0 = 0.f, aU1 = 0.f, aW0 = 0.f, aW1 = 0.f;
        if (ti != tj) {
            #pragma unroll
            for (int jj = 0; jj < 8; jj++) {
                float cj = nc[jj];
                #pragma unroll
                for (int ii = 0; ii < 8; ii++) {
                    float v = a[ii] + cj;
                    float u = fmaxf(v, -0.9f);
                    float w = fmaxf(v, 0.0f);
                    if (ii & 1) { aU1 += u; aW1 = fmaf(w, w, aW1); }
                    else        { aU0 += u; aW0 = fmaf(w, w, aW0); }
                }
            }
        } else {
            int ib = ty * 8, jb = tx * 8;
            #pragma unroll
            for (int jj = 0; jj < 8; jj++) {
                float cj = nc[jj];
                #pragma unroll
                for (int ii = 0; ii < 8; ii++) {
                    if (jb + jj > ib + ii) {
                        float v = a[ii] + cj;
                        float u = fmaxf(v, -0.9f);
                        float w = fmaxf(v, 0.0f);
                        if (ii & 1) { aU1 += u; aW1 = fmaf(w, w, aW1); }
                        else        { aU0 += u; aW0 = fmaf(w, w, aW0); }
                    }
                }
            }
        }
        contrib = 5.0f * (aW0 + aW1) - (aU0 + aU1);
    } else {
        // ---- same-label class tiles ----------------------------------------
        // G = 4p + z(15z-3) - 5w^2 - 0.95, p=relu(x), z=min(p,.1), w=relu(x-.9)
        int s = bid - APB;
        int b = s / (NCLS * CT); int rr = s % (NCLS * CT);
        int c = rr / CT;         int t = rr % CT;
        int ti = 0;
        while (t >= NTC - ti) { t -= NTC - ti; ti++; }
        int tj = ti + t;
        int M = g_Mc[b][c];
        if (tj * 128 < M) {
            const float* ca = g_cls_a [b] + c * CAP;
            const float* cn = g_cls_nb[b] + c * CAP;
            if (tid < 128) s_a[tid]        = ca[ti * 128 + tid];
            else           s_nc[tid - 128] = cn[tj * 128 + (tid - 128)];
            __syncthreads();
            int ty = tid >> 4, tx = tid & 15;
            float a8[8], n8[8];
            #pragma unroll
            for (int k = 0; k < 8; k++) { a8[k] = s_a[ty * 8 + k]; n8[k] = s_nc[tx * 8 + k]; }
            float accP = 0.f, accZQ = 0.f, accW = 0.f;
            if (ti != tj) {
                #pragma unroll
                for (int jj = 0; jj < 8; jj++) {
                    float nbj = n8[jj];
                    #pragma unroll
                    for (int ii = 0; ii < 8; ii++) {
                        float x = a8[ii] + nbj;
                        float p = fmaxf(x, 0.0f);
                        float z = fminf(p, 0.1f);
                        float w = fmaxf(x - 0.9f, 0.0f);
                        float q = fmaf(z, 15.0f, -3.0f);
                        accP += p;
                        accZQ = fmaf(z, q, accZQ);
                        accW  = fmaf(w, w, accW);
                    }
                }
            } else {
                #pragma unroll
                for (int jj = 0; jj < 8; jj++) {
                    float nbj = n8[jj]; int cc = tx * 8 + jj;
                    #pragma unroll
                    for (int ii = 0; ii < 8; ii++) {
                        if (cc > ty * 8 + ii) {
                            float x = a8[ii] + nbj;
                            float p = fmaxf(x, 0.0f);
                            float z = fminf(p, 0.1f);
                            float w = fmaxf(x - 0.9f, 0.0f);
                            float q = fmaf(z, 15.0f, -3.0f);
                            accP += p;
                            accZQ = fmaf(z, q, accZQ);
                            accW  = fmaf(w, w, accW);
                        }
                    }
                }
            }
            contrib = fmaf(4.0f, accP, accZQ) - 5.0f * accW;
            if (tid == 0)
                contrib -= 0.95f * (float)((ti != tj) ? 128 * 128 : (128 * 127) / 2);
        }
    }

    // ---- block reduce + atomic + last-block finalize ------------------------
    #pragma unroll
    for (int o = 16; o; o >>= 1)
        contrib += __shfl_xor_sync(0xffffffffu, contrib, o);
    int warp = tid >> 5, lane = tid & 31;
    if (lane == 0) s_part[warp] = contrib;
    __syncthreads();
    if (tid == 0) {
        float tot = 0.f;
        #pragma unroll
        for (int k = 0; k < 8; k++) tot += s_part[k];
        atomicAdd(&g_acc, (double)tot);
        __threadfence();
        unsigned cdone = atomicAdd(&g_cnt, 1u);
        if (cdone == (unsigned)(GRID2 - 1)) {
            double acc = *((volatile double*)&g_acc);
            out[0] = (float)(acc / (NP * (double)BS) + 0.05);
            g_acc = 0.0;      // restore invariants for next replay
            g_cnt = 0u;
        }
    }
}

extern "C" void kernel_launch(void* const* d_in, const int* in_sizes, int n_in,
                              void* d_out, int out_size) {
    const float* yp = (const float*)d_in[0];
    const int*   yt = (const int*)d_in[1];
    const int*   sm = (const int*)d_in[2];

    k1<<<GRID1, 256>>>(yp, yt, sm);
    k2<<<GRID2, 256>>>((float*)d_out);
}

// round 12
// speedup vs baseline: 1.4515x; 1.4515x over previous
#include <cuda_runtime.h>

namespace {
constexpr int BS = 4, P = 4096, HW = 512 * 512;
constexpr int NT = 32;                      // 128-wide tiles per dim
constexpr int NTILES = NT * (NT + 1) / 2;   // 528 upper-tri tiles
constexpr int GRID = BS * NTILES;           // 2112 blocks
constexpr double NP = 8386560.0;            // P*(P-1)/2
}

__device__ double g_acc;          // zero-init; reset by finalizing block
__device__ unsigned g_cnt;        // zero-init; reset by finalizing block

__global__ __launch_bounds__(256) void pair_k(const float* __restrict__ yp,
                                              const int*   __restrict__ yt,
                                              const int*   __restrict__ sm,
                                              float* __restrict__ out) {
    __shared__ float s_a[128];  __shared__ int s_ta[128];   // rows: pred, label
    __shared__ float s_nc[128]; __shared__ int s_tc[128];   // cols: -relu(pred), label
    __shared__ float s_part[8];

    int bid = blockIdx.x, tid = threadIdx.x;
    int b = bid / NTILES, t = bid % NTILES;
    int ti = 0;
    while (t >= NT - ti) { t -= NT - ti; ti++; }   // upper-tri decode (cheap)
    int tj = ti + t;

    // fused gather: coalesced idx load, scattered data loads (L2-resident
    // after first wave; overlapped across all 2112 blocks)
    if (tid < 128) {
        int idx = sm[b * P + ti * 128 + tid];
        s_a[tid]  = yp[b * HW + idx];
        s_ta[tid] = yt[b * HW + idx];
    } else {
        int u = tid - 128;
        int idx = sm[b * P + tj * 128 + u];
        s_nc[u] = -fmaxf(yp[b * HW + idx], 0.0f);
        s_tc[u] = yt[b * HW + idx];
    }
    __syncthreads();

    int tx = tid & 15, ty = tid >> 4;
    float a[8]; int ta[8]; float nc[8]; int tc[8];
    #pragma unroll
    for (int k = 0; k < 8; k++) {
        a[k]  = s_a[ty * 8 + k];
        ta[k] = s_ta[ty * 8 + k];
        nc[k] = s_nc[tx * 8 + k];
        tc[k] = s_tc[tx * 8 + k];
    }

    float acc0 = 0.0f, acc1 = 0.0f;
    if (ti != tj) {
        // interior tile: all 64 pairs valid (j > i guaranteed)
        #pragma unroll
        for (int jj = 0; jj < 8; jj++) {
            float cj = nc[jj]; int tcv = tc[jj];
            #pragma unroll
            for (int ii = 0; ii < 8; ii++) {
                float d = a[ii] + cj;                 // pred_i - relu(pred_j)
                float p = fmaxf(d, 0.0f);             // pi_pred
                float q = 1.0f - p;
                bool eq = (ta[ii] == tcv);
                float y = eq ? p : q;                 // huber argument
                float z  = fminf(y, 0.1f);
                float t1 = fmaf(5.0f, z, -1.0f);      // 5z-1 (FFMA-imm)
                float h  = fmaf(z, t1, y);            // = 5z^2 + (y-z) = huber(y)
                float s  = eq ? 3.0f : 1.0f;
                if (ii & 1) acc1 = fmaf(s, h, acc1);
                else        acc0 = fmaf(s, h, acc0);
            }
        }
    } else {
        // diagonal tile: mask j > i
        int ib = ty * 8, jb = tx * 8;
        #pragma unroll
        for (int jj = 0; jj < 8; jj++) {
            float cj = nc[jj]; int tcv = tc[jj];
            #pragma unroll
            for (int ii = 0; ii < 8; ii++) {
                if (jb + jj > ib + ii) {
                    float d = a[ii] + cj;
                    float p = fmaxf(d, 0.0f);
                    float q = 1.0f - p;
                    bool eq = (ta[ii] == tcv);
                    float y = eq ? p : q;
                    float z  = fminf(y, 0.1f);
                    float t1 = fmaf(5.0f, z, -1.0f);
                    float h  = fmaf(z, t1, y);
                    float s  = eq ? 3.0f : 1.0f;
                    if (ii & 1) acc1 = fmaf(s, h, acc1);
                    else        acc0 = fmaf(s, h, acc0);
                }
            }
        }
    }
    float acc = acc0 + acc1;

    // block reduce + single atomic + last-block finalize (no waits anywhere)
    #pragma unroll
    for (int o = 16; o; o >>= 1)
        acc += __shfl_xor_sync(0xffffffffu, acc, o);
    int warp = tid >> 5, lane = tid & 31;
    if (lane == 0) s_part[warp] = acc;
    __syncthreads();
    if (tid == 0) {
        float tot = 0.0f;
        #pragma unroll
        for (int k = 0; k < 8; k++) tot += s_part[k];
        atomicAdd(&g_acc, (double)tot);
        __threadfence();
        unsigned cdone = atomicAdd(&g_cnt, 1u);
        if (cdone == (unsigned)(GRID - 1)) {
            double total = *((volatile double*)&g_acc);
            out[0] = (float)(total / (NP * (double)BS));
            g_acc = 0.0;      // restore invariants for next graph replay
            g_cnt = 0u;
        }
    }
}

extern "C" void kernel_launch(void* const* d_in, const int* in_sizes, int n_in,
                              void* d_out, int out_size) {
    const float* yp = (const float*)d_in[0];
    const int*   yt = (const int*)d_in[1];
    const int*   sm = (const int*)d_in[2];

    pair_k<<<GRID, 256>>>(yp, yt, sm, (float*)d_out);
}